// round 8
// baseline (speedup 1.0000x reference)
#include <cuda_runtime.h>
#include <cuda_bf16.h>
#include <cstdint>

// BatchHardLoss round 7: bf16 mma.sync, symmetry, 128x256 CTA tile (64x64 warp
// tiles, occ 1), 3-deep 32KB B ring, job = (I,[J,J+1]) with diagonal singles
// via B duplication + scale folded into poly-exp coefficients.

#define BATCH 8192
#define DIMK  256
#define NCLS  512
#define GAMMA 0.001f

static __device__ float g_all[BATCH];
static __device__ float g_pos[BATCH];
static __device__ float g_same[BATCH];
static __device__ int   g_cnt[NCLS];
static __device__ int   g_members[NCLS * 16];
static __device__ __nv_bfloat16 g_Xb[BATCH * DIMK];

constexpr int BM = 128;
constexpr int NBLK = BATCH / BM;              // 64
constexpr int GRID = 132;                     // 132 x 8 jobs = 1056
constexpr int JOBS_PER_CTA = 8;
constexpr int AKCHUNK = 16384;                // A: 128 rows x 128B
constexpr int BKCHUNK = 32768;                // B: 256 rows x 128B
constexpr int ATILE = 65536;
constexpr int BRING = 3 * BKCHUNK;            // 96KB
constexpr int SMEM_DYN = ATILE + BRING;       // 160KB

#define SW128(o) ((o) ^ (((o) >> 3) & 0x70))

__device__ __forceinline__ void cp_async16(uint32_t dst, const void* src) {
    asm volatile("cp.async.cg.shared.global [%0], [%1], 16;\n" :: "r"(dst), "l"(src));
}
#define CP_COMMIT() asm volatile("cp.async.commit_group;\n" ::: "memory")
#define CP_WAIT(N)  asm volatile("cp.async.wait_group %0;\n" :: "n"(N) : "memory")

#define PACK2(d, a, b)    asm("mov.b64 %0, {%1,%2};" : "=l"(d) : "f"(a), "f"(b))
#define UNPACK2(a, b, s)  asm("mov.b64 {%0,%1}, %2;" : "=f"(a), "=f"(b) : "l"(s))
#define MUL2(d, a, b)     asm("mul.rn.f32x2 %0, %1, %2;" : "=l"(d) : "l"(a), "l"(b))
#define ADD2(d, a, b)     asm("add.rn.f32x2 %0, %1, %2;" : "=l"(d) : "l"(a), "l"(b))
#define FMA2(d, a, b, c)  asm("fma.rn.f32x2 %0, %1, %2, %3;" : "=l"(d) : "l"(a), "l"(b), "l"(c))

// ---------------- small kernels ----------------

__global__ void bhl_zero_cnt_kernel() {
    int i = threadIdx.x + blockIdx.x * blockDim.x;
    if (i < NCLS) g_cnt[i] = 0;
}

__global__ void bhl_convert_kernel(const float* __restrict__ X,
                                   const int* __restrict__ T,
                                   float* __restrict__ out) {
    int i = blockIdx.x * blockDim.x + threadIdx.x;
    float4 v = ((const float4*)X)[i];
    uint32_t lo = ((uint32_t)__bfloat16_as_ushort(__float2bfloat16_rn(v.y)) << 16)
                |  (uint32_t)__bfloat16_as_ushort(__float2bfloat16_rn(v.x));
    uint32_t hi = ((uint32_t)__bfloat16_as_ushort(__float2bfloat16_rn(v.w)) << 16)
                |  (uint32_t)__bfloat16_as_ushort(__float2bfloat16_rn(v.z));
    ((uint2*)g_Xb)[i] = make_uint2(lo, hi);
    if (i < BATCH) {
        g_all[i] = 0.0f;
        int c = T[i];
        int s = atomicAdd(&g_cnt[c], 1);
        if (s < 16) g_members[c * 16 + s] = i;
    }
    if (i == 0) out[0] = 0.0f;
}

// ---------------- main kernel ----------------

__device__ __forceinline__ void load_tileA(uint32_t sdst, const char* srcRow0, int tid) {
#pragma unroll
    for (int i = 0; i < 16; i++) {
        int s = i * 256 + tid;
        int row = s >> 5;
        int seg = s & 31;
        int chunk = seg >> 3, w = seg & 7;
        uint32_t soff = chunk * AKCHUNK + SW128(row * 128 + w * 16);
        cp_async16(sdst + soff, srcRow0 + (size_t)row * 512 + seg * 16);
    }
}

// B chunk: 256 rows x 128B (k-chunk kc), rows masked for diagonal singles
__device__ __forceinline__ void load_chunkB(uint32_t sdst, const char* srcRow0,
                                            int kc, int tid, int rowmask) {
#pragma unroll
    for (int i = 0; i < 8; i++) {
        int s = i * 256 + tid;            // 0..2047
        int n = s >> 3, w = s & 7;
        int rr = n & rowmask;
        uint32_t soff = SW128(n * 128 + w * 16);
        cp_async16(sdst + soff, srcRow0 + (size_t)rr * 512 + kc * 128 + w * 16);
    }
}

__global__ __launch_bounds__(256, 1)
void bhl_main_kernel() {
    extern __shared__ char dynsmem[];

    const int tid  = threadIdx.x;
    const int lane = tid & 31;
    const int wid  = tid >> 5;
    const int wm   = wid >> 2;            // 0..1 : M half
    const int wn   = wid & 3;             // 0..3 : 64-col slice of 256
    const int bid  = blockIdx.x;

    // decode job start
    int I = 0, rem = bid * JOBS_PER_CTA;
    for (;;) { int c = (65 - I) >> 1; if (rem < c) break; rem -= c; I++; }
    int k = rem;

    auto jobJS = [](int I_, int k_, int& J_, bool& s_) {
        int L = 64 - I_;
        if (L & 1) { s_ = (k_ == 0); J_ = s_ ? I_ : I_ + 2 * k_ - 1; }
        else       { s_ = false;     J_ = I_ + 2 * k_; }
    };

    int J; bool sgl;
    jobJS(I, k, J, sgl);

    const uint32_t sb = (uint32_t)__cvta_generic_to_shared(dynsmem);
    const uint32_t aBase = sb;
    const uint32_t bBase = sb + ATILE;

    const char* Xb = (const char*)g_Xb;

    load_tileA(aBase, Xb + (size_t)I * BM * 512, tid);
    load_chunkB(bBase, Xb + (size_t)J * BM * 512, 0, tid, sgl ? 127 : 255);
    CP_COMMIT();
    load_chunkB(bBase + BKCHUNK, Xb + (size_t)J * BM * 512, 1, tid, sgl ? 127 : 255);
    CP_COMMIT();

    float acc[4][8][4];
#pragma unroll
    for (int a = 0; a < 4; a++)
#pragma unroll
        for (int b = 0; b < 8; b++)
#pragma unroll
            for (int c = 0; c < 4; c++) acc[a][b][c] = 0.0f;

    unsigned long long G2, P4, P3, P2, P1, P0, ZERO2;
    unsigned long long accR[8], colAcc[8];
    {
        const float g = GAMMA, z = 0.0f;
        PACK2(G2, g, g); PACK2(ZERO2, z, z);
        P4 = P3 = P2 = P1 = P0 = ZERO2;
#pragma unroll
        for (int i = 0; i < 8; i++) { accR[i] = ZERO2; colAcc[i] = ZERO2; }
    }
    const float zf = 0.0f;

    int oldI = 0, oldJ = 0;
    bool haveOld = false, oldSingle = false;
    bool reloadedA = false;
    int gchunk = 0;

    auto setPoly = [&](bool s_) {
        float sc = s_ ? 0.5f : 1.0f;
        float p4 = sc * (1.0f / 24.0f), p3 = sc * (1.0f / 6.0f), p2 = sc * 0.5f;
        PACK2(P4, p4, p4); PACK2(P3, p3, p3); PACK2(P2, p2, p2);
        PACK2(P1, sc, sc); PACK2(P0, sc, sc);
    };

    auto epilogue_and_colflush = [&]() {
#pragma unroll
        for (int mt = 0; mt < 4; mt++) {
#pragma unroll
            for (int nt = 0; nt < 8; nt++) {
                unsigned long long d2, w2, e2;
                PACK2(d2, acc[mt][nt][0], acc[mt][nt][1]);
                MUL2(w2, d2, G2);
                FMA2(e2, w2, P4, P3);
                FMA2(e2, e2, w2, P2);
                FMA2(e2, e2, w2, P1);
                FMA2(e2, e2, w2, P0);
                ADD2(accR[mt * 2], accR[mt * 2], e2);
                ADD2(colAcc[nt], colAcc[nt], e2);

                PACK2(d2, acc[mt][nt][2], acc[mt][nt][3]);
                MUL2(w2, d2, G2);
                FMA2(e2, w2, P4, P3);
                FMA2(e2, e2, w2, P2);
                FMA2(e2, e2, w2, P1);
                FMA2(e2, e2, w2, P0);
                ADD2(accR[mt * 2 + 1], accR[mt * 2 + 1], e2);
                ADD2(colAcc[nt], colAcc[nt], e2);
            }
        }
        const int blkj = oldJ + (wn >> 1);
        const bool doFlush = (!oldSingle) && (blkj != oldI);
#pragma unroll
        for (int nt = 0; nt < 8; nt++) {
            float vlo, vhi;
            UNPACK2(vlo, vhi, colAcc[nt]);
#pragma unroll
            for (int o = 4; o <= 16; o <<= 1) {
                vlo += __shfl_xor_sync(0xffffffffu, vlo, o);
                vhi += __shfl_xor_sync(0xffffffffu, vhi, o);
            }
            if (doFlush && lane < 4) {
                int cb = (wn & 1) * 64 + nt * 8 + 2 * lane;
                atomicAdd(&g_all[blkj * BM + cb], vlo);
                atomicAdd(&g_all[blkj * BM + cb + 1], vhi);
            }
            colAcc[nt] = ZERO2;
        }
    };

    auto rowflush = [&](int Iblk) {
#pragma unroll
        for (int i = 0; i < 8; i++) {
            float vlo, vhi;
            UNPACK2(vlo, vhi, accR[i]);
            float v = vlo + vhi;
            v += __shfl_xor_sync(0xffffffffu, v, 1);
            v += __shfl_xor_sync(0xffffffffu, v, 2);
            if ((lane & 3) == 0) {
                int r = wm * 64 + (i >> 1) * 16 + (lane >> 2) + (i & 1) * 8;
                atomicAdd(&g_all[Iblk * BM + r], v);
            }
            accR[i] = ZERO2;
        }
    };

    for (int pi = 0; pi < JOBS_PER_CTA; ++pi) {
        const bool last = (pi == JOBS_PER_CTA - 1);
        int In = I, kn = k + 1;
        if (kn == ((65 - I) >> 1)) { In = I + 1; kn = 0; }
        int Jn; bool sgln;
        jobJS(In, kn, Jn, sgln);

        const char* Brow  = Xb + (size_t)J  * BM * 512;
        const char* BrowN = Xb + (size_t)Jn * BM * 512;
        const int maskC = sgl ? 127 : 255;
        const int maskN = sgln ? 127 : 255;

        for (int kc = 0; kc < 4; kc++) {
            if (kc == 0 && reloadedA) { CP_WAIT(0); reloadedA = false; }
            else { CP_WAIT(1); }
            __syncthreads();

            if (kc == 0 && haveOld) { epilogue_and_colflush(); haveOld = false; }

            const uint32_t aC = aBase + (uint32_t)kc * AKCHUNK;
            const uint32_t bC = bBase + (uint32_t)(gchunk % 3) * BKCHUNK;

#pragma unroll
            for (int ks = 0; ks < 4; ks++) {
                uint32_t af[4][4];
#pragma unroll
                for (int mt = 0; mt < 4; mt++) {
                    int row = wm * 64 + mt * 16 + (lane & 15);
                    int kseg = ks * 2 + (lane >> 4);
                    uint32_t addr = aC + SW128(row * 128 + kseg * 16);
                    asm volatile("ldmatrix.sync.aligned.m8n8.x4.shared.b16 {%0,%1,%2,%3}, [%4];\n"
                                 : "=r"(af[mt][0]), "=r"(af[mt][1]), "=r"(af[mt][2]), "=r"(af[mt][3])
                                 : "r"(addr));
                }
#pragma unroll
                for (int q = 0; q < 4; q++) {
                    int m = lane >> 3, r = lane & 7;
                    int nIdx = wn * 64 + q * 16 + ((m >> 1) << 3) + r;
                    int kseg = ks * 2 + (m & 1);
                    uint32_t b0, b1, b2, b3;
                    uint32_t addr = bC + SW128(nIdx * 128 + kseg * 16);
                    asm volatile("ldmatrix.sync.aligned.m8n8.x4.shared.b16 {%0,%1,%2,%3}, [%4];\n"
                                 : "=r"(b0), "=r"(b1), "=r"(b2), "=r"(b3) : "r"(addr));
                    if (kc == 0 && ks == 0) {
#pragma unroll
                        for (int mt = 0; mt < 4; mt++) {
                            asm volatile(
                                "mma.sync.aligned.m16n8k16.row.col.f32.bf16.bf16.f32 "
                                "{%0,%1,%2,%3}, {%4,%5,%6,%7}, {%8,%9}, {%10,%10,%10,%10};\n"
                                : "=f"(acc[mt][2 * q][0]), "=f"(acc[mt][2 * q][1]),
                                  "=f"(acc[mt][2 * q][2]), "=f"(acc[mt][2 * q][3])
                                : "r"(af[mt][0]), "r"(af[mt][1]), "r"(af[mt][2]), "r"(af[mt][3]),
                                  "r"(b0), "r"(b1), "f"(zf));
                            asm volatile(
                                "mma.sync.aligned.m16n8k16.row.col.f32.bf16.bf16.f32 "
                                "{%0,%1,%2,%3}, {%4,%5,%6,%7}, {%8,%9}, {%10,%10,%10,%10};\n"
                                : "=f"(acc[mt][2 * q + 1][0]), "=f"(acc[mt][2 * q + 1][1]),
                                  "=f"(acc[mt][2 * q + 1][2]), "=f"(acc[mt][2 * q + 1][3])
                                : "r"(af[mt][0]), "r"(af[mt][1]), "r"(af[mt][2]), "r"(af[mt][3]),
                                  "r"(b2), "r"(b3), "f"(zf));
                        }
                    } else {
#pragma unroll
                        for (int mt = 0; mt < 4; mt++) {
                            asm volatile(
                                "mma.sync.aligned.m16n8k16.row.col.f32.bf16.bf16.f32 "
                                "{%0,%1,%2,%3}, {%4,%5,%6,%7}, {%8,%9}, {%0,%1,%2,%3};\n"
                                : "+f"(acc[mt][2 * q][0]), "+f"(acc[mt][2 * q][1]),
                                  "+f"(acc[mt][2 * q][2]), "+f"(acc[mt][2 * q][3])
                                : "r"(af[mt][0]), "r"(af[mt][1]), "r"(af[mt][2]), "r"(af[mt][3]),
                                  "r"(b0), "r"(b1));
                            asm volatile(
                                "mma.sync.aligned.m16n8k16.row.col.f32.bf16.bf16.f32 "
                                "{%0,%1,%2,%3}, {%4,%5,%6,%7}, {%8,%9}, {%0,%1,%2,%3};\n"
                                : "+f"(acc[mt][2 * q + 1][0]), "+f"(acc[mt][2 * q + 1][1]),
                                  "+f"(acc[mt][2 * q + 1][2]), "+f"(acc[mt][2 * q + 1][3])
                                : "r"(af[mt][0]), "r"(af[mt][1]), "r"(af[mt][2]), "r"(af[mt][3]),
                                  "r"(b2), "r"(b3));
                        }
                    }
                }
            }

            uint32_t pSlot = bBase + (uint32_t)((gchunk + 2) % 3) * BKCHUNK;
            if (kc < 2) {
                load_chunkB(pSlot, Brow, kc + 2, tid, maskC);
            } else if (!last) {
                load_chunkB(pSlot, BrowN, kc - 2, tid, maskN);
            }
            CP_COMMIT();
            gchunk++;
        }

        oldI = I; oldJ = J; oldSingle = sgl; haveOld = true;
        setPoly(sgl);

        if (last) {
            epilogue_and_colflush(); haveOld = false;
            rowflush(I);
        } else if (In != I) {
            __syncthreads();
            epilogue_and_colflush(); haveOld = false;
            rowflush(I);
            load_tileA(aBase, Xb + (size_t)In * BM * 512, tid);
            CP_COMMIT();
            reloadedA = true;
        }
        I = In; k = kn; J = Jn; sgl = sgln;
    }
}

// ---------------- exact same-class correction (fp32) ----------------

__global__ __launch_bounds__(256)
void bhl_corr_kernel(const float* __restrict__ X) {
    __shared__ float rows[16][260];
    __shared__ int sm[16];
    const int c = blockIdx.x, tid = threadIdx.x;
    int K = g_cnt[c];
    if (K > 16) K = 16;
    if (tid < 16) sm[tid] = (tid < K) ? g_members[c * 16 + tid] : 0;
    __syncthreads();
#pragma unroll
    for (int f = tid; f < 1024; f += 256) {
        int row = f >> 6, q = f & 63;
        if (row < K) {
            float4 v = *(const float4*)(X + (size_t)sm[row] * DIMK + q * 4);
            *(float4*)&rows[row][q * 4] = v;
        }
    }
    __syncthreads();
    const int i = tid >> 4, j = tid & 15;
    const float4* ri = (const float4*)&rows[i][0];
    const float4* rj = (const float4*)&rows[j][0];
    float d0 = 0.0f, d1 = 0.0f, d2 = 0.0f, d3 = 0.0f;
#pragma unroll
    for (int d = 0; d < 64; d++) {
        float4 a = ri[d], b = rj[d];
        d0 += a.x * b.x; d1 += a.y * b.y; d2 += a.z * b.z; d3 += a.w * b.w;
    }
    float dot = (d0 + d1) + (d2 + d3);
    float w = fminf(fmaxf(dot * GAMMA, -16.0f), 16.0f);
    const bool valid = (i < K) && (j < K);
    float epos  = (valid && i != j) ? __expf(-w) : 0.0f;
    float esame = valid ? __expf(w) : 0.0f;
#pragma unroll
    for (int o = 8; o; o >>= 1) {
        epos  += __shfl_xor_sync(0xffffffffu, epos, o);
        esame += __shfl_xor_sync(0xffffffffu, esame, o);
    }
    if (j == 0 && i < K) {
        g_pos[sm[i]]  = epos;
        g_same[sm[i]] = esame;
    }
}

__global__ void bhl_finalize_kernel(float* __restrict__ out) {
    __shared__ float red[256];
    const int tid = threadIdx.x;
    const int r = blockIdx.x * 256 + tid;
    red[tid] = __logf(g_pos[r] * (g_all[r] - g_same[r]));
    __syncthreads();
    for (int o = 128; o; o >>= 1) {
        if (tid < o) red[tid] += red[tid + o];
        __syncthreads();
    }
    if (tid == 0) atomicAdd(out, red[0] * (1.0f / (float)BATCH));
}

extern "C" void kernel_launch(void* const* d_in, const int* in_sizes, int n_in,
                              void* d_out, int out_size) {
    const float* X = (const float*)d_in[0];
    const int*   T = (const int*)d_in[1];
    float* out = (float*)d_out;

    cudaFuncSetAttribute(bhl_main_kernel, cudaFuncAttributeMaxDynamicSharedMemorySize, SMEM_DYN);

    bhl_zero_cnt_kernel<<<2, 256>>>();
    bhl_convert_kernel<<<(BATCH * DIMK / 4) / 256, 256>>>(X, T, out);
    bhl_corr_kernel<<<NCLS, 256>>>(X);
    bhl_main_kernel<<<GRID, 256, SMEM_DYN>>>();
    bhl_finalize_kernel<<<BATCH / 256, 256>>>(out);
}